// round 5
// baseline (speedup 1.0000x reference)
#include <cuda_runtime.h>
#include <math.h>

#define H 1024
#define V 50257
#define S 2048

// W_out L2-prefetch plan: stage first PF_TOTAL rows (96 MB < ~126 MB L2)
// into L2 during the latency-bound small-kernel phase.
#define PF_ROWS_PER_BLOCK 32            // 32 rows * 4KB = 128KB per prefetch block

// ---------------- device scratch (__device__ globals; alloc-free rule) -----
__device__ float g_gi[3 * H];
__device__ float g_gh[3 * H];
__device__ float g_cat[2 * H];  // [ctx ; h_new]
__device__ float g_attn[S];     // attn logits (pre-softmax)
__device__ float g_comb[H];
__device__ float g_sum[1];      // sum of exp(vocab logits)

__device__ __forceinline__ float warp_sum(float v) {
#pragma unroll
    for (int o = 16; o > 0; o >>= 1) v += __shfl_xor_sync(0xffffffffu, v, o);
    return v;
}
__device__ __forceinline__ float warp_max(float v) {
#pragma unroll
    for (int o = 16; o > 0; o >>= 1) v = fmaxf(v, __shfl_xor_sync(0xffffffffu, v, o));
    return v;
}
__device__ __forceinline__ float dot4(float4 a, float4 b) {
    return a.x * b.x + a.y * b.y + a.z * b.z + a.w * b.w;
}
__device__ __forceinline__ float block_sum256(float v, float* sh) {
    int t = threadIdx.x;
    v = warp_sum(v);
    if ((t & 31) == 0) sh[t >> 5] = v;
    __syncthreads();
    if (t < 32) {
        float x = (t < 8) ? sh[t] : 0.f;
        x = warp_sum(x);
        if (t == 0) sh[0] = x;
    }
    __syncthreads();
    float r = sh[0];
    __syncthreads();
    return r;
}
__device__ __forceinline__ float block_max256(float v, float* sh) {
    int t = threadIdx.x;
    v = warp_max(v);
    if ((t & 31) == 0) sh[t >> 5] = v;
    __syncthreads();
    if (t < 32) {
        float x = (t < 8) ? sh[t] : -1e30f;
        x = warp_max(x);
        if (t == 0) sh[0] = x;
    }
    __syncthreads();
    float r = sh[0];
    __syncthreads();
    return r;
}

// Prefetch PF_ROWS_PER_BLOCK rows of W_out (row-major, H floats/row) into L2.
// 32 rows * 32 lines(128B)/row = 1024 lines; 256 threads -> 4 lines each.
__device__ __forceinline__ void prefetch_wout(const float* Wo, int row0) {
    const char* base = (const char*)Wo + (size_t)row0 * H * sizeof(float);
#pragma unroll
    for (int j = 0; j < 4; j++) {
        size_t line = (size_t)(threadIdx.x + j * 256) * 128;
        asm volatile("prefetch.global.L2 [%0];" :: "l"(base + line));
    }
}

// 1) gates: blocks [0,768) compute (2 warps/row, 4 rows/blk);
//    blocks [768,1024) prefetch W_out rows [0, 8192).
__global__ void __launch_bounds__(256) k_gates(
        const int* __restrict__ ids, const float* __restrict__ emb,
        const float* __restrict__ Wih, const float* __restrict__ Whh,
        const float* __restrict__ bih, const float* __restrict__ bhh,
        const float* __restrict__ h, const float* __restrict__ Wo) {
    if (blockIdx.x >= 768) {
        prefetch_wout(Wo, (blockIdx.x - 768) * PF_ROWS_PER_BLOCK);
        return;
    }
    __shared__ float sh_x[H];
    __shared__ float p1[8], p2[8];
    int t = threadIdx.x;
    size_t erow = (size_t)ids[0] * H;
#pragma unroll
    for (int j = 0; j < 4; j++) {
        int i = t + j * 256;
        sh_x[i] = fmaxf(emb[erow + i], 0.0f);
    }
    __syncthreads();

    int w = t >> 5, lane = t & 31;
    int row = blockIdx.x * 4 + (w >> 1);
    int half = w & 1;
    const float4* wi = (const float4*)(Wih + (size_t)row * H) + half * 128;
    const float4* wh = (const float4*)(Whh + (size_t)row * H) + half * 128;
    const float4* xv = (const float4*)sh_x + half * 128;
    const float4* hv = (const float4*)h + half * 128;

    float4 a0 = __ldcs(wi + lane),      a1 = __ldcs(wi + 32 + lane),
           a2 = __ldcs(wi + 64 + lane), a3 = __ldcs(wi + 96 + lane);
    float4 b0 = __ldcs(wh + lane),      b1 = __ldcs(wh + 32 + lane),
           b2 = __ldcs(wh + 64 + lane), b3 = __ldcs(wh + 96 + lane);
    float4 h0 = hv[lane], h1 = hv[32 + lane], h2 = hv[64 + lane], h3 = hv[96 + lane];

    float s1 = dot4(a0, xv[lane]) + dot4(a1, xv[32 + lane])
             + dot4(a2, xv[64 + lane]) + dot4(a3, xv[96 + lane]);
    float s2 = dot4(b0, h0) + dot4(b1, h1) + dot4(b2, h2) + dot4(b3, h3);
    s1 = warp_sum(s1); s2 = warp_sum(s2);
    if (lane == 0) { p1[w] = s1; p2[w] = s2; }
    __syncthreads();
    if (t < 4) {
        int r = blockIdx.x * 4 + t;
        g_gi[r] = p1[2 * t] + p1[2 * t + 1] + bih[r];
        g_gh[r] = p2[2 * t] + p2[2 * t + 1] + bhh[r];
    }
}

// 2) attn logits (h_new fused): blocks [0,512) compute; [512,768) prefetch
//    W_out rows [8192, 16384).
__global__ void __launch_bounds__(256) k_attn_logits(
        const float* __restrict__ enc, const float* __restrict__ h,
        float* __restrict__ out, const float* __restrict__ Wo) {
    if (blockIdx.x >= 512) {
        prefetch_wout(Wo, 8192 + (blockIdx.x - 512) * PF_ROWS_PER_BLOCK);
        return;
    }
    __shared__ float sh_h[H];
    __shared__ float p[8];
    int t = threadIdx.x;
#pragma unroll
    for (int j = 0; j < 4; j++) {
        int i = t + j * 256;
        float r = 1.0f / (1.0f + expf(-(g_gi[i] + g_gh[i])));
        float z = 1.0f / (1.0f + expf(-(g_gi[H + i] + g_gh[H + i])));
        float n = tanhf(g_gi[2 * H + i] + r * g_gh[2 * H + i]);
        float hn = (1.0f - z) * n + z * h[i];
        sh_h[i] = hn;
        if (blockIdx.x == 0) {
            g_cat[i] = 0.0f;
            g_cat[H + i] = hn;
            out[V + i] = hn;                   // output slot 2: h_new
        }
    }
    if (blockIdx.x == 0 && t == 0) g_sum[0] = 0.0f;
    __syncthreads();

    int w = t >> 5, lane = t & 31;
    int row = blockIdx.x * 4 + (w >> 1);
    int half = w & 1;
    const float4* e = (const float4*)(enc + (size_t)row * H) + half * 128;
    const float4* hv = (const float4*)sh_h + half * 128;

    float4 a0 = e[lane],      a1 = e[32 + lane],
           a2 = e[64 + lane], a3 = e[96 + lane];
    float s = dot4(a0, hv[lane]) + dot4(a1, hv[32 + lane])
            + dot4(a2, hv[64 + lane]) + dot4(a3, hv[96 + lane]);
    s = warp_sum(s);
    if (lane == 0) p[w] = s;
    __syncthreads();
    if (t < 4) g_attn[blockIdx.x * 4 + t] = p[2 * t] + p[2 * t + 1];
}

// 3) ctx (softmax fused), 1D grid: blocks [0,128) compute (4 col-blks x 32
//    s-chunks); blocks [128,256) prefetch W_out rows [16384, 20480).
__global__ void __launch_bounds__(256) k_ctx(
        const float* __restrict__ enc, float* __restrict__ out,
        const float* __restrict__ Wo) {
    if (blockIdx.x >= 128) {
        prefetch_wout(Wo, 16384 + (blockIdx.x - 128) * PF_ROWS_PER_BLOCK);
        return;
    }
    __shared__ float sh_red[8];
    __shared__ float sh_a[64];
    int t = threadIdx.x;
    int col = (blockIdx.x & 3) * 256 + t;
    int s0 = (blockIdx.x >> 2) * 64;

    const float4* lv = (const float4*)g_attn;
    float4 l0 = lv[t], l1 = lv[t + 256];
    float m = fmaxf(fmaxf(l0.x, l0.y), fmaxf(l0.z, l0.w));
    m = fmaxf(m, fmaxf(fmaxf(l1.x, l1.y), fmaxf(l1.z, l1.w)));
    float M = block_max256(m, sh_red);
    float e = expf(l0.x - M) + expf(l0.y - M) + expf(l0.z - M) + expf(l0.w - M)
            + expf(l1.x - M) + expf(l1.y - M) + expf(l1.z - M) + expf(l1.w - M);
    float SUM = block_sum256(e, sh_red);
    float inv = 1.0f / SUM;

    // block 0 publishes attn weights (scalar stores: out+V+H not 16B-aligned)
    if (blockIdx.x == 0) {
        float* ao = out + V + H;
        int b0 = t * 4;
        ao[b0 + 0] = expf(l0.x - M) * inv;
        ao[b0 + 1] = expf(l0.y - M) * inv;
        ao[b0 + 2] = expf(l0.z - M) * inv;
        ao[b0 + 3] = expf(l0.w - M) * inv;
        int b1 = (t + 256) * 4;
        ao[b1 + 0] = expf(l1.x - M) * inv;
        ao[b1 + 1] = expf(l1.y - M) * inv;
        ao[b1 + 2] = expf(l1.z - M) * inv;
        ao[b1 + 3] = expf(l1.w - M) * inv;
    }

    if (t < 64) sh_a[t] = expf(g_attn[s0 + t] - M) * inv;
    __syncthreads();

    float acc = 0.f;
#pragma unroll 8
    for (int s = 0; s < 64; s++) {
        acc += sh_a[s] * enc[(size_t)(s0 + s) * H + col];
    }
    atomicAdd(&g_cat[col], acc);
}

// 4) comb: blocks [0,256) compute (2 warps/row over 2H, 4 rows/blk);
//    blocks [256,384) prefetch W_out rows [20480, 24576).
__global__ void __launch_bounds__(256) k_comb(
        const float* __restrict__ Wc, const float* __restrict__ bc,
        const float* __restrict__ Wo) {
    if (blockIdx.x >= 256) {
        prefetch_wout(Wo, 20480 + (blockIdx.x - 256) * PF_ROWS_PER_BLOCK);
        return;
    }
    __shared__ float p[8];
    int t = threadIdx.x;
    int w = t >> 5, lane = t & 31;
    int row = blockIdx.x * 4 + (w >> 1);
    int half = w & 1;
    const float4* wv = (const float4*)(Wc + (size_t)row * 2 * H) + half * 256;
    const float4* vv = (const float4*)g_cat + half * 256;

    float4 a0 = __ldcs(wv + lane),       a1 = __ldcs(wv + 32 + lane),
           a2 = __ldcs(wv + 64 + lane),  a3 = __ldcs(wv + 96 + lane),
           a4 = __ldcs(wv + 128 + lane), a5 = __ldcs(wv + 160 + lane),
           a6 = __ldcs(wv + 192 + lane), a7 = __ldcs(wv + 224 + lane);
    float s = dot4(a0, vv[lane])        + dot4(a1, vv[32 + lane])
            + dot4(a2, vv[64 + lane])   + dot4(a3, vv[96 + lane])
            + dot4(a4, vv[128 + lane])  + dot4(a5, vv[160 + lane])
            + dot4(a6, vv[192 + lane])  + dot4(a7, vv[224 + lane]);
    s = warp_sum(s);
    if (lane == 0) p[w] = s;
    __syncthreads();
    if (t < 4) {
        int r = blockIdx.x * 4 + t;
        g_comb[r] = tanhf(p[2 * t] + p[2 * t + 1] + bc[r]);
    }
}

// 5) vocab logits -> out[0:V] + fused exp-sum. DEFAULT cached loads so the
//    L2-prefetched rows hit; tail rows stream from DRAM concurrently.
__global__ void __launch_bounds__(256) k_vocab(
        const float* __restrict__ Wo, const float* __restrict__ bo,
        float* __restrict__ out) {
    __shared__ float sh_c[H];
    __shared__ float sh_e[8];
    int t = threadIdx.x;
#pragma unroll
    for (int j = 0; j < 4; j++) sh_c[t + j * 256] = g_comb[t + j * 256];
    __syncthreads();

    int w = t >> 5, lane = t & 31;
    int row = blockIdx.x * 8 + w;              // 6283 blocks
    float myexp = 0.f;
    if (row < V) {
        const float4* wv = (const float4*)(Wo + (size_t)row * H);
        const float4* c = (const float4*)sh_c;
        float4 a0 = __ldg(wv + lane),       a1 = __ldg(wv + 32 + lane),
               a2 = __ldg(wv + 64 + lane),  a3 = __ldg(wv + 96 + lane),
               a4 = __ldg(wv + 128 + lane), a5 = __ldg(wv + 160 + lane),
               a6 = __ldg(wv + 192 + lane), a7 = __ldg(wv + 224 + lane);
        float s = dot4(a0, c[lane])        + dot4(a1, c[32 + lane])
                + dot4(a2, c[64 + lane])   + dot4(a3, c[96 + lane])
                + dot4(a4, c[128 + lane])  + dot4(a5, c[160 + lane])
                + dot4(a6, c[192 + lane])  + dot4(a7, c[224 + lane]);
        s = warp_sum(s);
        if (lane == 0) {
            float logit = s + bo[row];
            out[row] = logit;
            myexp = expf(logit);
        }
    }
    if (lane == 0) sh_e[w] = myexp;
    __syncthreads();
    if (t == 0) {
        float s = sh_e[0] + sh_e[1] + sh_e[2] + sh_e[3]
                + sh_e[4] + sh_e[5] + sh_e[6] + sh_e[7];
        atomicAdd(&g_sum[0], s);
    }
}

// 6) out[i] -= log(sum exp)   (vectorized, V = 12564*4 + 1)
__global__ void __launch_bounds__(256) k_logprob(float* __restrict__ out) {
    int i = blockIdx.x * 256 + threadIdx.x;
    float lse = logf(g_sum[0]);
    float4* o4 = (float4*)out;
    if (i < 12564) {
        float4 v = o4[i];
        v.x -= lse; v.y -= lse; v.z -= lse; v.w -= lse;
        o4[i] = v;
    } else if (i == 12564) {
        out[V - 1] -= lse;
    }
}

extern "C" void kernel_launch(void* const* d_in, const int* in_sizes, int n_in,
                              void* d_out, int out_size) {
    const int*   ids  = (const int*)  d_in[0];
    const float* hid  = (const float*)d_in[1];
    const float* enc  = (const float*)d_in[2];
    const float* emb  = (const float*)d_in[3];
    const float* Wih  = (const float*)d_in[4];
    const float* Whh  = (const float*)d_in[5];
    const float* bih  = (const float*)d_in[6];
    const float* bhh  = (const float*)d_in[7];
    const float* Wc   = (const float*)d_in[8];
    const float* bc   = (const float*)d_in[9];
    const float* Wo   = (const float*)d_in[10];
    const float* bo   = (const float*)d_in[11];
    float* out = (float*)d_out;                // [log_probs V | h_new H | attn S]

    k_gates<<<768 + 256, 256>>>(ids, emb, Wih, Whh, bih, bhh, hid, Wo);
    k_attn_logits<<<512 + 256, 256>>>(enc, hid, out, Wo);
    k_ctx<<<128 + 128, 256>>>(enc, out, Wo);
    k_comb<<<256 + 128, 256>>>(Wc, bc, Wo);
    k_vocab<<<(V + 7) / 8, 256>>>(Wo, bo, out);
    k_logprob<<<(V / 4 + 256) / 256, 256>>>(out);
}

// round 6
// speedup vs baseline: 1.1079x; 1.1079x over previous
#include <cuda_runtime.h>
#include <math.h>

#define H 1024
#define V 50257
#define S 2048

#define NBLOCKS 296            // 148 SMs x 2 blocks/SM, all co-resident
#define NTHREADS 256
#define NWARPS (NBLOCKS * 8)   // 2368
#define VROWS_PER_WARP 22      // ceil(V / NWARPS)

// ---------------- device scratch (__device__ globals; alloc-free rule) -----
__device__ float g_gi[3 * H];
__device__ float g_gh[3 * H];
__device__ float g_cat[2 * H];      // [ctx ; h_new]
__device__ float g_attn[S];         // attn logits (pre-softmax)
__device__ float g_comb[H];
__device__ float g_sum[1];          // sum of exp(vocab logits)
__device__ unsigned g_bar[5];       // generation-counting grid barriers (never reset)

__device__ __forceinline__ float warp_sum(float v) {
#pragma unroll
    for (int o = 16; o > 0; o >>= 1) v += __shfl_xor_sync(0xffffffffu, v, o);
    return v;
}
__device__ __forceinline__ float warp_max(float v) {
#pragma unroll
    for (int o = 16; o > 0; o >>= 1) v = fmaxf(v, __shfl_xor_sync(0xffffffffu, v, o));
    return v;
}
__device__ __forceinline__ float dot4(float4 a, float4 b) {
    return a.x * b.x + a.y * b.y + a.z * b.z + a.w * b.w;
}

// Grid-wide barrier, generation-counting: arrivals from replay r are exactly
// [r*N, (r+1)*N), so each arriver waits for ceil-to-next-multiple-of-N.
// Monotonic counter => safe across graph replays without any reset.
__device__ __forceinline__ void grid_barrier(int i) {
    __syncthreads();
    if (threadIdx.x == 0) {
        __threadfence();
        unsigned v = atomicAdd(&g_bar[i], 1u);
        unsigned target = (v / NBLOCKS) * NBLOCKS + NBLOCKS;
        volatile unsigned* p = &g_bar[i];
        while (*p < target) { __nanosleep(64); }
        __threadfence();
    }
    __syncthreads();
}

__global__ void __launch_bounds__(NTHREADS, 2) mega(
        const int* __restrict__ ids, const float* __restrict__ emb,
        const float* __restrict__ Wih, const float* __restrict__ Whh,
        const float* __restrict__ bih, const float* __restrict__ bhh,
        const float* __restrict__ h,
        const float* __restrict__ Wc, const float* __restrict__ bc,
        const float* __restrict__ Wo, const float* __restrict__ bo,
        const float* __restrict__ enc, float* __restrict__ out) {
    __shared__ float sh_x[H];       // relu(emb) in S1, reused as comb in S6
    __shared__ float sh_h[H];       // h_new
    __shared__ float sh_red[8];
    __shared__ float sh_a[64];
    __shared__ float sh_e[8];

    const int t = threadIdx.x;
    const int w = t >> 5, lane = t & 31;
    const int gw = blockIdx.x * 8 + w;          // global warp id [0, 2368)

    // ---- S1: gates. 3072 row-tasks over 2368 warps (stride loop). ----
#pragma unroll
    for (int j = 0; j < 4; j++) {
        int i = t + j * 256;
        sh_x[i] = fmaxf(emb[(size_t)ids[0] * H + i], 0.0f);
    }
    __syncthreads();
    for (int r = gw; r < 3 * H; r += NWARPS) {
        const float4* wi = (const float4*)(Wih + (size_t)r * H);
        const float4* wh = (const float4*)(Whh + (size_t)r * H);
        const float4* xv = (const float4*)sh_x;
        const float4* hv = (const float4*)h;
        float4 a0 = __ldcs(wi + lane),       a1 = __ldcs(wi + 32 + lane),
               a2 = __ldcs(wi + 64 + lane),  a3 = __ldcs(wi + 96 + lane),
               a4 = __ldcs(wi + 128 + lane), a5 = __ldcs(wi + 160 + lane),
               a6 = __ldcs(wi + 192 + lane), a7 = __ldcs(wi + 224 + lane);
        float4 b0 = __ldcs(wh + lane),       b1 = __ldcs(wh + 32 + lane),
               b2 = __ldcs(wh + 64 + lane),  b3 = __ldcs(wh + 96 + lane),
               b4 = __ldcs(wh + 128 + lane), b5 = __ldcs(wh + 160 + lane),
               b6 = __ldcs(wh + 192 + lane), b7 = __ldcs(wh + 224 + lane);
        float s1 = dot4(a0, xv[lane])       + dot4(a1, xv[32 + lane])
                 + dot4(a2, xv[64 + lane])  + dot4(a3, xv[96 + lane])
                 + dot4(a4, xv[128 + lane]) + dot4(a5, xv[160 + lane])
                 + dot4(a6, xv[192 + lane]) + dot4(a7, xv[224 + lane]);
        float s2 = dot4(b0, hv[lane])       + dot4(b1, hv[32 + lane])
                 + dot4(b2, hv[64 + lane])  + dot4(b3, hv[96 + lane])
                 + dot4(b4, hv[128 + lane]) + dot4(b5, hv[160 + lane])
                 + dot4(b6, hv[192 + lane]) + dot4(b7, hv[224 + lane]);
        s1 = warp_sum(s1); s2 = warp_sum(s2);
        if (lane == 0) { g_gi[r] = s1 + bih[r]; g_gh[r] = s2 + bhh[r]; }
    }
    grid_barrier(0);

    // ---- S2: every block computes h_new into sh_h (reads are L2-hot). ----
#pragma unroll
    for (int j = 0; j < 4; j++) {
        int i = t + j * 256;
        float r = 1.0f / (1.0f + expf(-(g_gi[i] + g_gh[i])));
        float z = 1.0f / (1.0f + expf(-(g_gi[H + i] + g_gh[H + i])));
        float n = tanhf(g_gi[2 * H + i] + r * g_gh[2 * H + i]);
        float hn = (1.0f - z) * n + z * h[i];
        sh_h[i] = hn;
        if (blockIdx.x == 0) {
            g_cat[i] = 0.0f;
            g_cat[H + i] = hn;
            out[V + i] = hn;                   // output slot 2: h_new
        }
    }
    if (blockIdx.x == 0 && t == 0) g_sum[0] = 0.0f;
    __syncthreads();

    // ---- S3: attn logits, warp per row (rows 0..2047). ----
    if (gw < S) {
        const float4* e = (const float4*)(enc + (size_t)gw * H);
        const float4* hv = (const float4*)sh_h;
        float4 a0 = e[lane],        a1 = e[32 + lane],
               a2 = e[64 + lane],   a3 = e[96 + lane],
               a4 = e[128 + lane],  a5 = e[160 + lane],
               a6 = e[192 + lane],  a7 = e[224 + lane];
        float s = dot4(a0, hv[lane])       + dot4(a1, hv[32 + lane])
                + dot4(a2, hv[64 + lane])  + dot4(a3, hv[96 + lane])
                + dot4(a4, hv[128 + lane]) + dot4(a5, hv[160 + lane])
                + dot4(a6, hv[192 + lane]) + dot4(a7, hv[224 + lane]);
        s = warp_sum(s);
        if (lane == 0) g_attn[gw] = s;
    }
    grid_barrier(1);

    // ---- S4: softmax (redundant per block) + ctx on blocks [0,128). ----
    if (blockIdx.x < 128) {
        const float4* lv = (const float4*)g_attn;
        float4 l0 = lv[t], l1 = lv[t + 256];
        float m = fmaxf(fmaxf(l0.x, l0.y), fmaxf(l0.z, l0.w));
        m = fmaxf(m, fmaxf(fmaxf(l1.x, l1.y), fmaxf(l1.z, l1.w)));
        // block max
        m = warp_max(m);
        if (lane == 0) sh_red[w] = m;
        __syncthreads();
        if (t < 32) {
            float x = (t < 8) ? sh_red[t] : -1e30f;
            x = warp_max(x);
            if (t == 0) sh_red[0] = x;
        }
        __syncthreads();
        float M = sh_red[0];
        __syncthreads();
        float e = expf(l0.x - M) + expf(l0.y - M) + expf(l0.z - M) + expf(l0.w - M)
                + expf(l1.x - M) + expf(l1.y - M) + expf(l1.z - M) + expf(l1.w - M);
        e = warp_sum(e);
        if (lane == 0) sh_red[w] = e;
        __syncthreads();
        if (t < 32) {
            float x = (t < 8) ? sh_red[t] : 0.f;
            x = warp_sum(x);
            if (t == 0) sh_red[0] = x;
        }
        __syncthreads();
        float inv = 1.0f / sh_red[0];

        if (blockIdx.x == 0) {                 // publish attn weights (scalar:
            float* ao = out + V + H;           // out+V+H not 16B-aligned)
            int b0 = t * 4;
            ao[b0 + 0] = expf(l0.x - M) * inv;
            ao[b0 + 1] = expf(l0.y - M) * inv;
            ao[b0 + 2] = expf(l0.z - M) * inv;
            ao[b0 + 3] = expf(l0.w - M) * inv;
            int b1 = (t + 256) * 4;
            ao[b1 + 0] = expf(l1.x - M) * inv;
            ao[b1 + 1] = expf(l1.y - M) * inv;
            ao[b1 + 2] = expf(l1.z - M) * inv;
            ao[b1 + 3] = expf(l1.w - M) * inv;
        }

        int col = (blockIdx.x & 3) * 256 + t;
        int s0 = (blockIdx.x >> 2) * 64;
        if (t < 64) sh_a[t] = expf(g_attn[s0 + t] - M) * inv;
        __syncthreads();
        float acc = 0.f;
#pragma unroll 8
        for (int s = 0; s < 64; s++)
            acc += sh_a[s] * enc[(size_t)(s0 + s) * H + col];
        atomicAdd(&g_cat[col], acc);
    }
    grid_barrier(2);

    // ---- S5: comb, warp per row (rows 0..1023), 2H-long dot. ----
    if (gw < H) {
        const float4* wv = (const float4*)(Wc + (size_t)gw * 2 * H);
        const float4* vv = (const float4*)g_cat;
        float s = 0.f;
#pragma unroll
        for (int half = 0; half < 2; half++) {
            const float4* wp = wv + half * 256;
            const float4* vp = vv + half * 256;
            float4 a0 = __ldcs(wp + lane),       a1 = __ldcs(wp + 32 + lane),
                   a2 = __ldcs(wp + 64 + lane),  a3 = __ldcs(wp + 96 + lane),
                   a4 = __ldcs(wp + 128 + lane), a5 = __ldcs(wp + 160 + lane),
                   a6 = __ldcs(wp + 192 + lane), a7 = __ldcs(wp + 224 + lane);
            s += dot4(a0, vp[lane])       + dot4(a1, vp[32 + lane])
               + dot4(a2, vp[64 + lane])  + dot4(a3, vp[96 + lane])
               + dot4(a4, vp[128 + lane]) + dot4(a5, vp[160 + lane])
               + dot4(a6, vp[192 + lane]) + dot4(a7, vp[224 + lane]);
        }
        s = warp_sum(s);
        if (lane == 0) g_comb[gw] = tanhf(s + bc[gw]);
    }
    grid_barrier(3);

    // ---- S6: vocab. 22 contiguous rows per warp + fused exp-sum. ----
#pragma unroll
    for (int j = 0; j < 4; j++) sh_x[t + j * 256] = g_comb[t + j * 256];
    __syncthreads();
    {
        const float4* c = (const float4*)sh_x;
        int base = gw * VROWS_PER_WARP;
        float esum = 0.f;
        for (int k = 0; k < VROWS_PER_WARP; k++) {
            int row = base + k;
            if (row >= V) break;
            const float4* wv = (const float4*)(Wo + (size_t)row * H);
            float4 a0 = __ldcs(wv + lane),       a1 = __ldcs(wv + 32 + lane),
                   a2 = __ldcs(wv + 64 + lane),  a3 = __ldcs(wv + 96 + lane),
                   a4 = __ldcs(wv + 128 + lane), a5 = __ldcs(wv + 160 + lane),
                   a6 = __ldcs(wv + 192 + lane), a7 = __ldcs(wv + 224 + lane);
            float s = dot4(a0, c[lane])       + dot4(a1, c[32 + lane])
                    + dot4(a2, c[64 + lane])  + dot4(a3, c[96 + lane])
                    + dot4(a4, c[128 + lane]) + dot4(a5, c[160 + lane])
                    + dot4(a6, c[192 + lane]) + dot4(a7, c[224 + lane]);
            s = warp_sum(s);
            if (lane == 0) {
                float logit = s + bo[row];
                out[row] = logit;
                esum += expf(logit);           // logits tiny: no stabilization
            }
        }
        if (lane == 0) sh_e[w] = esum;
        __syncthreads();
        if (t == 0) {
            float s = sh_e[0] + sh_e[1] + sh_e[2] + sh_e[3]
                    + sh_e[4] + sh_e[5] + sh_e[6] + sh_e[7];
            atomicAdd(&g_sum[0], s);
        }
    }
    grid_barrier(4);

    // ---- S7: log-softmax subtract (grid-stride, coalesced). ----
    {
        float lse = logf(g_sum[0]);
        for (int i = blockIdx.x * NTHREADS + t; i < V; i += NBLOCKS * NTHREADS)
            out[i] -= lse;
    }
}

extern "C" void kernel_launch(void* const* d_in, const int* in_sizes, int n_in,
                              void* d_out, int out_size) {
    const int*   ids  = (const int*)  d_in[0];
    const float* hid  = (const float*)d_in[1];
    const float* enc  = (const float*)d_in[2];
    const float* emb  = (const float*)d_in[3];
    const float* Wih  = (const float*)d_in[4];
    const float* Whh  = (const float*)d_in[5];
    const float* bih  = (const float*)d_in[6];
    const float* bhh  = (const float*)d_in[7];
    const float* Wc   = (const float*)d_in[8];
    const float* bc   = (const float*)d_in[9];
    const float* Wo   = (const float*)d_in[10];
    const float* bo   = (const float*)d_in[11];
    float* out = (float*)d_out;                // [log_probs V | h_new H | attn S]

    mega<<<NBLOCKS, NTHREADS>>>(ids, emb, Wih, Whh, bih, bhh, hid,
                                Wc, bc, Wo, bo, enc, out);
}

// round 7
// speedup vs baseline: 1.1554x; 1.0429x over previous
#include <cuda_runtime.h>
#include <math.h>

#define H 1024
#define V 50257
#define S 2048

#define NBLOCKS 296            // 148 SMs x 2 blocks/SM, co-resident
#define NTHREADS 256
#define NWARPS (NBLOCKS * 8)   // 2368

// ---------------- device scratch (__device__ globals; alloc-free rule) -----
__device__ float g_gi[3 * H];
__device__ float g_gh[3 * H];
__device__ float g_cat[2 * H];      // [ctx ; h_new]
__device__ float g_attn[S];         // attn logits (pre-softmax)
__device__ float g_comb[H];
__device__ float g_sum[1];          // sum of exp(vocab logits)
__device__ unsigned g_bar[3];       // generation-counting grid barriers (never reset)

__device__ __forceinline__ float warp_sum(float v) {
#pragma unroll
    for (int o = 16; o > 0; o >>= 1) v += __shfl_xor_sync(0xffffffffu, v, o);
    return v;
}
__device__ __forceinline__ float warp_max(float v) {
#pragma unroll
    for (int o = 16; o > 0; o >>= 1) v = fmaxf(v, __shfl_xor_sync(0xffffffffu, v, o));
    return v;
}
__device__ __forceinline__ float dot4(float4 a, float4 b) {
    return a.x * b.x + a.y * b.y + a.z * b.z + a.w * b.w;
}

// Grid-wide barrier, generation-counting (monotonic; graph-replay safe).
__device__ __forceinline__ void grid_barrier(int i) {
    __syncthreads();
    if (threadIdx.x == 0) {
        __threadfence();
        unsigned v = atomicAdd(&g_bar[i], 1u);
        unsigned target = (v / NBLOCKS) * NBLOCKS + NBLOCKS;
        volatile unsigned* p = &g_bar[i];
        while (*p < target) { __nanosleep(64); }
        __threadfence();
    }
    __syncthreads();
}

// ===== Kernel A: stages 1-5 (gates, h_new, attn, softmax+ctx, comb) =====
__global__ void __launch_bounds__(NTHREADS, 2) megaA(
        const int* __restrict__ ids, const float* __restrict__ emb,
        const float* __restrict__ Wih, const float* __restrict__ Whh,
        const float* __restrict__ bih, const float* __restrict__ bhh,
        const float* __restrict__ h,
        const float* __restrict__ Wc, const float* __restrict__ bc,
        const float* __restrict__ enc, float* __restrict__ out) {
    __shared__ float sh_x[H];       // relu(emb)
    __shared__ float sh_h[H];       // h_new
    __shared__ float sh_red[8];
    __shared__ float sh_a[64];

    const int t = threadIdx.x;
    const int w = t >> 5, lane = t & 31;
    const int gw = blockIdx.x * 8 + w;          // global warp id [0, 2368)

    // ---- S1: gates. 3072 row-tasks over 2368 warps. ----
#pragma unroll
    for (int j = 0; j < 4; j++) {
        int i = t + j * 256;
        sh_x[i] = fmaxf(emb[(size_t)ids[0] * H + i], 0.0f);
    }
    __syncthreads();
    for (int r = gw; r < 3 * H; r += NWARPS) {
        const float4* wi = (const float4*)(Wih + (size_t)r * H);
        const float4* wh = (const float4*)(Whh + (size_t)r * H);
        const float4* xv = (const float4*)sh_x;
        const float4* hv = (const float4*)h;
        float4 a0 = __ldcs(wi + lane),       a1 = __ldcs(wi + 32 + lane),
               a2 = __ldcs(wi + 64 + lane),  a3 = __ldcs(wi + 96 + lane),
               a4 = __ldcs(wi + 128 + lane), a5 = __ldcs(wi + 160 + lane),
               a6 = __ldcs(wi + 192 + lane), a7 = __ldcs(wi + 224 + lane);
        float4 b0 = __ldcs(wh + lane),       b1 = __ldcs(wh + 32 + lane),
               b2 = __ldcs(wh + 64 + lane),  b3 = __ldcs(wh + 96 + lane),
               b4 = __ldcs(wh + 128 + lane), b5 = __ldcs(wh + 160 + lane),
               b6 = __ldcs(wh + 192 + lane), b7 = __ldcs(wh + 224 + lane);
        float s1 = dot4(a0, xv[lane])       + dot4(a1, xv[32 + lane])
                 + dot4(a2, xv[64 + lane])  + dot4(a3, xv[96 + lane])
                 + dot4(a4, xv[128 + lane]) + dot4(a5, xv[160 + lane])
                 + dot4(a6, xv[192 + lane]) + dot4(a7, xv[224 + lane]);
        float s2 = dot4(b0, hv[lane])       + dot4(b1, hv[32 + lane])
                 + dot4(b2, hv[64 + lane])  + dot4(b3, hv[96 + lane])
                 + dot4(b4, hv[128 + lane]) + dot4(b5, hv[160 + lane])
                 + dot4(b6, hv[192 + lane]) + dot4(b7, hv[224 + lane]);
        s1 = warp_sum(s1); s2 = warp_sum(s2);
        if (lane == 0) { g_gi[r] = s1 + bih[r]; g_gh[r] = s2 + bhh[r]; }
    }
    grid_barrier(0);

    // ---- S2: every block computes h_new into sh_h (L2-hot reads). ----
#pragma unroll
    for (int j = 0; j < 4; j++) {
        int i = t + j * 256;
        float r = 1.0f / (1.0f + expf(-(g_gi[i] + g_gh[i])));
        float z = 1.0f / (1.0f + expf(-(g_gi[H + i] + g_gh[H + i])));
        float n = tanhf(g_gi[2 * H + i] + r * g_gh[2 * H + i]);
        float hn = (1.0f - z) * n + z * h[i];
        sh_h[i] = hn;
        if (blockIdx.x == 0) {
            g_cat[i] = 0.0f;
            g_cat[H + i] = hn;
            out[V + i] = hn;                   // output slot 2: h_new
        }
    }
    if (blockIdx.x == 0 && t == 0) g_sum[0] = 0.0f;
    __syncthreads();

    // ---- S3: attn logits, warp per row. ----
    if (gw < S) {
        const float4* e = (const float4*)(enc + (size_t)gw * H);
        const float4* hv = (const float4*)sh_h;
        float4 a0 = e[lane],        a1 = e[32 + lane],
               a2 = e[64 + lane],   a3 = e[96 + lane],
               a4 = e[128 + lane],  a5 = e[160 + lane],
               a6 = e[192 + lane],  a7 = e[224 + lane];
        float s = dot4(a0, hv[lane])       + dot4(a1, hv[32 + lane])
                + dot4(a2, hv[64 + lane])  + dot4(a3, hv[96 + lane])
                + dot4(a4, hv[128 + lane]) + dot4(a5, hv[160 + lane])
                + dot4(a6, hv[192 + lane]) + dot4(a7, hv[224 + lane]);
        s = warp_sum(s);
        if (lane == 0) g_attn[gw] = s;
    }
    grid_barrier(1);

    // ---- S4: softmax (redundant per block) + ctx on blocks [0,128). ----
    if (blockIdx.x < 128) {
        const float4* lv = (const float4*)g_attn;
        float4 l0 = lv[t], l1 = lv[t + 256];
        float m = fmaxf(fmaxf(l0.x, l0.y), fmaxf(l0.z, l0.w));
        m = fmaxf(m, fmaxf(fmaxf(l1.x, l1.y), fmaxf(l1.z, l1.w)));
        m = warp_max(m);
        if (lane == 0) sh_red[w] = m;
        __syncthreads();
        if (t < 32) {
            float x = (t < 8) ? sh_red[t] : -1e30f;
            x = warp_max(x);
            if (t == 0) sh_red[0] = x;
        }
        __syncthreads();
        float M = sh_red[0];
        __syncthreads();
        float e = expf(l0.x - M) + expf(l0.y - M) + expf(l0.z - M) + expf(l0.w - M)
                + expf(l1.x - M) + expf(l1.y - M) + expf(l1.z - M) + expf(l1.w - M);
        e = warp_sum(e);
        if (lane == 0) sh_red[w] = e;
        __syncthreads();
        if (t < 32) {
            float x = (t < 8) ? sh_red[t] : 0.f;
            x = warp_sum(x);
            if (t == 0) sh_red[0] = x;
        }
        __syncthreads();
        float inv = 1.0f / sh_red[0];

        if (blockIdx.x == 0) {                 // publish attn weights (scalar:
            float* ao = out + V + H;           // out+V+H not 16B-aligned)
            int b0 = t * 4;
            ao[b0 + 0] = expf(l0.x - M) * inv;
            ao[b0 + 1] = expf(l0.y - M) * inv;
            ao[b0 + 2] = expf(l0.z - M) * inv;
            ao[b0 + 3] = expf(l0.w - M) * inv;
            int b1 = (t + 256) * 4;
            ao[b1 + 0] = expf(l1.x - M) * inv;
            ao[b1 + 1] = expf(l1.y - M) * inv;
            ao[b1 + 2] = expf(l1.z - M) * inv;
            ao[b1 + 3] = expf(l1.w - M) * inv;
        }

        int col = (blockIdx.x & 3) * 256 + t;
        int s0 = (blockIdx.x >> 2) * 64;
        if (t < 64) sh_a[t] = expf(g_attn[s0 + t] - M) * inv;
        __syncthreads();
        float acc = 0.f;
#pragma unroll 8
        for (int s = 0; s < 64; s++)
            acc += sh_a[s] * enc[(size_t)(s0 + s) * H + col];
        atomicAdd(&g_cat[col], acc);
    }
    grid_barrier(2);

    // ---- S5: comb, warp per row (rows 0..1023), 2H-long dot. ----
    if (gw < H) {
        const float4* wv = (const float4*)(Wc + (size_t)gw * 2 * H);
        const float4* vv = (const float4*)g_cat;
        float s = 0.f;
#pragma unroll
        for (int half = 0; half < 2; half++) {
            const float4* wp = wv + half * 256;
            const float4* vp = vv + half * 256;
            float4 a0 = __ldcs(wp + lane),       a1 = __ldcs(wp + 32 + lane),
                   a2 = __ldcs(wp + 64 + lane),  a3 = __ldcs(wp + 96 + lane),
                   a4 = __ldcs(wp + 128 + lane), a5 = __ldcs(wp + 160 + lane),
                   a6 = __ldcs(wp + 192 + lane), a7 = __ldcs(wp + 224 + lane);
            s += dot4(a0, vp[lane])       + dot4(a1, vp[32 + lane])
               + dot4(a2, vp[64 + lane])  + dot4(a3, vp[96 + lane])
               + dot4(a4, vp[128 + lane]) + dot4(a5, vp[160 + lane])
               + dot4(a6, vp[192 + lane]) + dot4(a7, vp[224 + lane]);
        }
        s = warp_sum(s);
        if (lane == 0) g_comb[gw] = tanhf(s + bc[gw]);
    }
}

// ===== Kernel B: vocab logits + fused exp-sum (full multi-wave grid) =====
__global__ void __launch_bounds__(256) k_vocab(
        const float* __restrict__ Wo, const float* __restrict__ bo,
        float* __restrict__ out) {
    __shared__ float sh_c[H];
    __shared__ float sh_e[8];
    int t = threadIdx.x;
#pragma unroll
    for (int j = 0; j < 4; j++) sh_c[t + j * 256] = g_comb[t + j * 256];
    __syncthreads();

    int w = t >> 5, lane = t & 31;
    int row = blockIdx.x * 8 + w;              // 6283 blocks
    float myexp = 0.f;
    if (row < V) {
        const float4* wv = (const float4*)(Wo + (size_t)row * H);
        const float4* c = (const float4*)sh_c;
        float4 a0 = __ldcs(wv + lane),       a1 = __ldcs(wv + 32 + lane),
               a2 = __ldcs(wv + 64 + lane),  a3 = __ldcs(wv + 96 + lane),
               a4 = __ldcs(wv + 128 + lane), a5 = __ldcs(wv + 160 + lane),
               a6 = __ldcs(wv + 192 + lane), a7 = __ldcs(wv + 224 + lane);
        float s = dot4(a0, c[lane])       + dot4(a1, c[32 + lane])
                + dot4(a2, c[64 + lane])  + dot4(a3, c[96 + lane])
                + dot4(a4, c[128 + lane]) + dot4(a5, c[160 + lane])
                + dot4(a6, c[192 + lane]) + dot4(a7, c[224 + lane]);
        s = warp_sum(s);
        if (lane == 0) {
            float logit = s + bo[row];
            out[row] = logit;
            myexp = expf(logit);               // logits tiny: no stabilization
        }
    }
    if (lane == 0) sh_e[w] = myexp;
    __syncthreads();
    if (t == 0) {
        float s = sh_e[0] + sh_e[1] + sh_e[2] + sh_e[3]
                + sh_e[4] + sh_e[5] + sh_e[6] + sh_e[7];
        atomicAdd(&g_sum[0], s);
    }
}

// ===== Kernel C: out[i] -= log(sum exp)  (V = 12564*4 + 1) =====
__global__ void __launch_bounds__(256) k_logprob(float* __restrict__ out) {
    int i = blockIdx.x * 256 + threadIdx.x;
    float lse = logf(g_sum[0]);
    float4* o4 = (float4*)out;
    if (i < 12564) {
        float4 v = o4[i];
        v.x -= lse; v.y -= lse; v.z -= lse; v.w -= lse;
        o4[i] = v;
    } else if (i == 12564) {
        out[V - 1] -= lse;
    }
}

extern "C" void kernel_launch(void* const* d_in, const int* in_sizes, int n_in,
                              void* d_out, int out_size) {
    const int*   ids  = (const int*)  d_in[0];
    const float* hid  = (const float*)d_in[1];
    const float* enc  = (const float*)d_in[2];
    const float* emb  = (const float*)d_in[3];
    const float* Wih  = (const float*)d_in[4];
    const float* Whh  = (const float*)d_in[5];
    const float* bih  = (const float*)d_in[6];
    const float* bhh  = (const float*)d_in[7];
    const float* Wc   = (const float*)d_in[8];
    const float* bc   = (const float*)d_in[9];
    const float* Wo   = (const float*)d_in[10];
    const float* bo   = (const float*)d_in[11];
    float* out = (float*)d_out;                // [log_probs V | h_new H | attn S]

    megaA<<<NBLOCKS, NTHREADS>>>(ids, emb, Wih, Whh, bih, bhh, hid,
                                 Wc, bc, enc, out);
    k_vocab<<<(V + 7) / 8, 256>>>(Wo, bo, out);
    k_logprob<<<(V / 4 + 256) / 256, 256>>>(out);
}

// round 8
// speedup vs baseline: 1.1899x; 1.0298x over previous
#include <cuda_runtime.h>
#include <math.h>

#define H 1024
#define V 50257
#define S 2048

#define NBLOCKS 296            // 148 SMs x 2 blocks/SM, co-resident
#define NTHREADS 256
#define NWARPS (NBLOCKS * 8)   // 2368

// ---------------- device scratch (__device__ globals; alloc-free rule) -----
__device__ float g_gi[3 * H];
__device__ float g_gh[3 * H];
__device__ float g_cat[2 * H];      // [unnormalized ctx ; h_new]
__device__ float g_attn[S];         // attn logits (raw)
__device__ float g_e[S];            // exp(logit - M), unnormalized
__device__ float g_comb[H];
__device__ float g_sum[1];          // sum of exp(vocab logits)
__device__ float g_Z[1];            // attn softmax partition sum
__device__ unsigned g_bar[4];       // generation-counting grid barriers (never reset)

__device__ __forceinline__ float warp_sum(float v) {
#pragma unroll
    for (int o = 16; o > 0; o >>= 1) v += __shfl_xor_sync(0xffffffffu, v, o);
    return v;
}
__device__ __forceinline__ float warp_max(float v) {
#pragma unroll
    for (int o = 16; o > 0; o >>= 1) v = fmaxf(v, __shfl_xor_sync(0xffffffffu, v, o));
    return v;
}
__device__ __forceinline__ float dot4(float4 a, float4 b) {
    return a.x * b.x + a.y * b.y + a.z * b.z + a.w * b.w;
}

// Grid-wide barrier, generation-counting (monotonic; graph-replay safe).
__device__ __forceinline__ void grid_barrier(int i) {
    __syncthreads();
    if (threadIdx.x == 0) {
        __threadfence();
        unsigned v = atomicAdd(&g_bar[i], 1u);
        unsigned target = (v / NBLOCKS) * NBLOCKS + NBLOCKS;
        volatile unsigned* p = &g_bar[i];
        while (*p < target) { }
        __threadfence();
    }
    __syncthreads();
}

// ===== Kernel A: front stages, MUFU-distributed =====
__global__ void __launch_bounds__(NTHREADS, 2) megaA(
        const int* __restrict__ ids, const float* __restrict__ emb,
        const float* __restrict__ Wih, const float* __restrict__ Whh,
        const float* __restrict__ bih, const float* __restrict__ bhh,
        const float* __restrict__ h,
        const float* __restrict__ Wc, const float* __restrict__ bc,
        const float* __restrict__ enc, float* __restrict__ out) {
    __shared__ float sh_x[H];       // relu(emb)
    __shared__ float sh_h[H];       // h_new
    __shared__ float sh_red[8];
    __shared__ float sh_a[64];

    const int t = threadIdx.x;
    const int w = t >> 5, lane = t & 31;
    const int gw = blockIdx.x * 8 + w;          // global warp id [0, 2368)

    // ---- S1: gates. 3072 row-tasks over 2368 warps. ----
#pragma unroll
    for (int j = 0; j < 4; j++) {
        int i = t + j * 256;
        sh_x[i] = fmaxf(emb[(size_t)ids[0] * H + i], 0.0f);
    }
    __syncthreads();
    for (int r = gw; r < 3 * H; r += NWARPS) {
        const float4* wi = (const float4*)(Wih + (size_t)r * H);
        const float4* wh = (const float4*)(Whh + (size_t)r * H);
        const float4* xv = (const float4*)sh_x;
        const float4* hv = (const float4*)h;
        float4 a0 = __ldcs(wi + lane),       a1 = __ldcs(wi + 32 + lane),
               a2 = __ldcs(wi + 64 + lane),  a3 = __ldcs(wi + 96 + lane),
               a4 = __ldcs(wi + 128 + lane), a5 = __ldcs(wi + 160 + lane),
               a6 = __ldcs(wi + 192 + lane), a7 = __ldcs(wi + 224 + lane);
        float4 b0 = __ldcs(wh + lane),       b1 = __ldcs(wh + 32 + lane),
               b2 = __ldcs(wh + 64 + lane),  b3 = __ldcs(wh + 96 + lane),
               b4 = __ldcs(wh + 128 + lane), b5 = __ldcs(wh + 160 + lane),
               b6 = __ldcs(wh + 192 + lane), b7 = __ldcs(wh + 224 + lane);
        float s1 = dot4(a0, xv[lane])       + dot4(a1, xv[32 + lane])
                 + dot4(a2, xv[64 + lane])  + dot4(a3, xv[96 + lane])
                 + dot4(a4, xv[128 + lane]) + dot4(a5, xv[160 + lane])
                 + dot4(a6, xv[192 + lane]) + dot4(a7, xv[224 + lane]);
        float s2 = dot4(b0, hv[lane])       + dot4(b1, hv[32 + lane])
                 + dot4(b2, hv[64 + lane])  + dot4(b3, hv[96 + lane])
                 + dot4(b4, hv[128 + lane]) + dot4(b5, hv[160 + lane])
                 + dot4(b6, hv[192 + lane]) + dot4(b7, hv[224 + lane]);
        s1 = warp_sum(s1); s2 = warp_sum(s2);
        if (lane == 0) { g_gi[r] = s1 + bih[r]; g_gh[r] = s2 + bhh[r]; }
    }
    grid_barrier(0);

    // ---- S2: h_new DISTRIBUTED (blocks 0..3 only -> 1024 threads total) ----
    if (blockIdx.x < 4) {
        int i = blockIdx.x * 256 + t;
        float r = 1.0f / (1.0f + expf(-(g_gi[i] + g_gh[i])));
        float z = 1.0f / (1.0f + expf(-(g_gi[H + i] + g_gh[H + i])));
        float n = tanhf(g_gi[2 * H + i] + r * g_gh[2 * H + i]);
        float hn = (1.0f - z) * n + z * h[i];
        g_cat[i] = 0.0f;                       // unnormalized ctx accumulator
        g_cat[H + i] = hn;
        out[V + i] = hn;                       // output slot 2: h_new
    }
    if (blockIdx.x == 4 && t == 0) { g_sum[0] = 0.0f; g_Z[0] = 0.0f; }
    grid_barrier(1);

    // ---- S3: attn logits, warp per row; h_new via L2 -> shared. ----
#pragma unroll
    for (int j = 0; j < 4; j++) sh_h[t + j * 256] = g_cat[H + t + j * 256];
    __syncthreads();
    if (gw < S) {
        const float4* e = (const float4*)(enc + (size_t)gw * H);
        const float4* hv = (const float4*)sh_h;
        float4 a0 = e[lane],        a1 = e[32 + lane],
               a2 = e[64 + lane],   a3 = e[96 + lane],
               a4 = e[128 + lane],  a5 = e[160 + lane],
               a6 = e[192 + lane],  a7 = e[224 + lane];
        float s = dot4(a0, hv[lane])       + dot4(a1, hv[32 + lane])
                + dot4(a2, hv[64 + lane])  + dot4(a3, hv[96 + lane])
                + dot4(a4, hv[128 + lane]) + dot4(a5, hv[160 + lane])
                + dot4(a6, hv[192 + lane]) + dot4(a7, hv[224 + lane]);
        s = warp_sum(s);
        if (lane == 0) g_attn[gw] = s;
    }
    grid_barrier(2);

    // ---- S4: blocks [0,128): max (MUFU-free, redundant), own-chunk exp only,
    //      unnormalized ctx accumulation + partial Z. ----
    if (blockIdx.x < 128) {
        float m = -1e30f;
#pragma unroll
        for (int j = 0; j < 8; j++) m = fmaxf(m, g_attn[t + j * 256]);
        m = warp_max(m);
        if (lane == 0) sh_red[w] = m;
        __syncthreads();
        if (t < 32) {
            float x = (t < 8) ? sh_red[t] : -1e30f;
            x = warp_max(x);
            if (t == 0) sh_red[0] = x;
        }
        __syncthreads();
        float M = sh_red[0];

        int cb = blockIdx.x & 3;               // col block [0,4)
        int s0 = (blockIdx.x >> 2) * 64;       // s-chunk base
        if (t < 64) sh_a[t] = expf(g_attn[s0 + t] - M);
        __syncthreads();

        if (cb == 0) {                         // one col-block per chunk owns Z + g_e
            if (t < 64) g_e[s0 + t] = sh_a[t];
            if (t == 0) {
                float z = 0.f;
#pragma unroll
                for (int k = 0; k < 64; k++) z += sh_a[k];
                atomicAdd(&g_Z[0], z);
            }
        }
        int col = cb * 256 + t;
        float acc = 0.f;
#pragma unroll 8
        for (int s = 0; s < 64; s++)
            acc += sh_a[s] * enc[(size_t)(s0 + s) * H + col];
        atomicAdd(&g_cat[col], acc);
    }
    grid_barrier(3);

    float invZ = 1.0f / g_Z[0];

    // ---- S5a: comb, warp per row (blocks 0..127 -> gw 0..1023). ----
    if (gw < H) {
        const float4* wv = (const float4*)(Wc + (size_t)gw * 2 * H);
        const float4* vv = (const float4*)g_cat;
        float sc_part[2];
#pragma unroll
        for (int half = 0; half < 2; half++) {
            const float4* wp = wv + half * 256;
            const float4* vp = vv + half * 256;
            float4 a0 = __ldcs(wp + lane),       a1 = __ldcs(wp + 32 + lane),
                   a2 = __ldcs(wp + 64 + lane),  a3 = __ldcs(wp + 96 + lane),
                   a4 = __ldcs(wp + 128 + lane), a5 = __ldcs(wp + 160 + lane),
                   a6 = __ldcs(wp + 192 + lane), a7 = __ldcs(wp + 224 + lane);
            sc_part[half] = dot4(a0, vp[lane])       + dot4(a1, vp[32 + lane])
                          + dot4(a2, vp[64 + lane])  + dot4(a3, vp[96 + lane])
                          + dot4(a4, vp[128 + lane]) + dot4(a5, vp[160 + lane])
                          + dot4(a6, vp[192 + lane]) + dot4(a7, vp[224 + lane]);
        }
        float s = sc_part[0] * invZ + sc_part[1];  // ctx part normalized by 1/Z
        s = warp_sum(s);
        if (lane == 0) g_comb[gw] = tanhf(s + bc[gw]);
    }
    // ---- S5b: attn output (blocks 128..135 -> 2048 threads). ----
    if (blockIdx.x >= 128 && blockIdx.x < 136) {
        int i = (blockIdx.x - 128) * 256 + t;
        out[V + H + i] = g_e[i] * invZ;        // scalar store (misaligned base)
    }
}

// ===== Kernel B: vocab logits + fused exp-sum (full multi-wave grid) =====
__global__ void __launch_bounds__(256) k_vocab(
        const float* __restrict__ Wo, const float* __restrict__ bo,
        float* __restrict__ out) {
    __shared__ float sh_c[H];
    __shared__ float sh_e[8];
    int t = threadIdx.x;
#pragma unroll
    for (int j = 0; j < 4; j++) sh_c[t + j * 256] = g_comb[t + j * 256];
    __syncthreads();

    int w = t >> 5, lane = t & 31;
    int row = blockIdx.x * 8 + w;              // 6283 blocks
    float myexp = 0.f;
    if (row < V) {
        const float4* wv = (const float4*)(Wo + (size_t)row * H);
        const float4* c = (const float4*)sh_c;
        float4 a0 = __ldcs(wv + lane),       a1 = __ldcs(wv + 32 + lane),
               a2 = __ldcs(wv + 64 + lane),  a3 = __ldcs(wv + 96 + lane),
               a4 = __ldcs(wv + 128 + lane), a5 = __ldcs(wv + 160 + lane),
               a6 = __ldcs(wv + 192 + lane), a7 = __ldcs(wv + 224 + lane);
        float s = dot4(a0, c[lane])       + dot4(a1, c[32 + lane])
                + dot4(a2, c[64 + lane])  + dot4(a3, c[96 + lane])
                + dot4(a4, c[128 + lane]) + dot4(a5, c[160 + lane])
                + dot4(a6, c[192 + lane]) + dot4(a7, c[224 + lane]);
        s = warp_sum(s);
        if (lane == 0) {
            float logit = s + bo[row];
            out[row] = logit;
            myexp = expf(logit);               // logits tiny: no stabilization
        }
    }
    if (lane == 0) sh_e[w] = myexp;
    __syncthreads();
    if (t == 0) {
        float s = sh_e[0] + sh_e[1] + sh_e[2] + sh_e[3]
                + sh_e[4] + sh_e[5] + sh_e[6] + sh_e[7];
        atomicAdd(&g_sum[0], s);
    }
}

// ===== Kernel C: out[i] -= log(sum exp)  (V = 12564*4 + 1) =====
__global__ void __launch_bounds__(256) k_logprob(float* __restrict__ out) {
    int i = blockIdx.x * 256 + threadIdx.x;
    float lse = logf(g_sum[0]);
    float4* o4 = (float4*)out;
    if (i < 12564) {
        float4 v = o4[i];
        v.x -= lse; v.y -= lse; v.z -= lse; v.w -= lse;
        o4[i] = v;
    } else if (i == 12564) {
        out[V - 1] -= lse;
    }
}

extern "C" void kernel_launch(void* const* d_in, const int* in_sizes, int n_in,
                              void* d_out, int out_size) {
    const int*   ids  = (const int*)  d_in[0];
    const float* hid  = (const float*)d_in[1];
    const float* enc  = (const float*)d_in[2];
    const float* emb  = (const float*)d_in[3];
    const float* Wih  = (const float*)d_in[4];
    const float* Whh  = (const float*)d_in[5];
    const float* bih  = (const float*)d_in[6];
    const float* bhh  = (const float*)d_in[7];
    const float* Wc   = (const float*)d_in[8];
    const float* bc   = (const float*)d_in[9];
    const float* Wo   = (const float*)d_in[10];
    const float* bo   = (const float*)d_in[11];
    float* out = (float*)d_out;                // [log_probs V | h_new H | attn S]

    megaA<<<NBLOCKS, NTHREADS>>>(ids, emb, Wih, Whh, bih, bhh, hid,
                                 Wc, bc, enc, out);
    k_vocab<<<(V + 7) / 8, 256>>>(Wo, bo, out);
    k_logprob<<<(V / 4 + 256) / 256, 256>>>(out);
}

// round 9
// speedup vs baseline: 1.1988x; 1.0075x over previous
#include <cuda_runtime.h>
#include <math.h>

#define H 1024
#define V 50257
#define S 2048

#define NBLOCKS 296            // 148 SMs x 2 blocks/SM, co-resident
#define NTHREADS 256
#define NWARPS (NBLOCKS * 8)   // 2368
#define NTASKS (6144)          // 3072 rows x {Wih, Whh}

// ---------------- device scratch (__device__ globals; alloc-free rule) -----
__device__ float g_gi[3 * H];
__device__ float g_gh[3 * H];
__device__ float g_cat[2 * H];      // [unnormalized ctx ; h_new]
__device__ float g_attn[S];         // attn logits (raw)
__device__ float g_e[S];            // exp(logit - M), unnormalized
__device__ float g_comb[H];
__device__ float g_sum[1];          // sum of exp(vocab logits)
__device__ float g_Z[1];            // attn softmax partition sum
__device__ unsigned g_bar[4];       // generation-counting grid barriers (never reset)

__device__ __forceinline__ float warp_sum(float v) {
#pragma unroll
    for (int o = 16; o > 0; o >>= 1) v += __shfl_xor_sync(0xffffffffu, v, o);
    return v;
}
__device__ __forceinline__ float warp_max(float v) {
#pragma unroll
    for (int o = 16; o > 0; o >>= 1) v = fmaxf(v, __shfl_xor_sync(0xffffffffu, v, o));
    return v;
}
__device__ __forceinline__ float dot4(float4 a, float4 b) {
    return a.x * b.x + a.y * b.y + a.z * b.z + a.w * b.w;
}

// Grid-wide barrier, generation-counting (monotonic; graph-replay safe).
__device__ __forceinline__ void grid_barrier(int i) {
    __syncthreads();
    if (threadIdx.x == 0) {
        __threadfence();
        unsigned v = atomicAdd(&g_bar[i], 1u);
        unsigned target = (v / NBLOCKS) * NBLOCKS + NBLOCKS;
        volatile unsigned* p = &g_bar[i];
        while (*p < target) { }
        __threadfence();
    }
    __syncthreads();
}

// one (row, matrix) task: 8 float4 loads + dot against smem vector
struct TaskRegs { float4 r0, r1, r2, r3, r4, r5, r6, r7; };

__device__ __forceinline__ void task_load(TaskRegs& T, const float4* wp, int lane) {
    T.r0 = __ldcs(wp + lane);        T.r1 = __ldcs(wp + 32 + lane);
    T.r2 = __ldcs(wp + 64 + lane);   T.r3 = __ldcs(wp + 96 + lane);
    T.r4 = __ldcs(wp + 128 + lane);  T.r5 = __ldcs(wp + 160 + lane);
    T.r6 = __ldcs(wp + 192 + lane);  T.r7 = __ldcs(wp + 224 + lane);
}
__device__ __forceinline__ float task_dot(const TaskRegs& T, const float4* v, int lane) {
    return dot4(T.r0, v[lane])        + dot4(T.r1, v[32 + lane])
         + dot4(T.r2, v[64 + lane])   + dot4(T.r3, v[96 + lane])
         + dot4(T.r4, v[128 + lane])  + dot4(T.r5, v[160 + lane])
         + dot4(T.r6, v[192 + lane])  + dot4(T.r7, v[224 + lane]);
}

// ===== Kernel A: front stages with cross-stage load decoupling =====
__global__ void __launch_bounds__(NTHREADS, 2) megaA(
        const int* __restrict__ ids, const float* __restrict__ emb,
        const float* __restrict__ Wih, const float* __restrict__ Whh,
        const float* __restrict__ bih, const float* __restrict__ bhh,
        const float* __restrict__ h,
        const float* __restrict__ Wc, const float* __restrict__ bc,
        const float* __restrict__ enc, float* __restrict__ out) {
    __shared__ float sh_x[H];       // relu(emb)
    __shared__ float sh_hid[H];     // old hidden h
    __shared__ float sh_h[H];       // h_new
    __shared__ float sh_red[8];
    __shared__ float sh_a[64];

    const int t = threadIdx.x;
    const int w = t >> 5, lane = t & 31;
    const int gw = blockIdx.x * 8 + w;          // global warp id [0, 2368)

    // ---- enc PRELOAD for S3 (independent of h_new): issue FIRST. ----
    float4 e0, e1, e2, e3, e4, e5, e6, e7;
    if (gw < S) {
        const float4* e = (const float4*)(enc + (size_t)gw * H);
        e0 = e[lane];        e1 = e[32 + lane];
        e2 = e[64 + lane];   e3 = e[96 + lane];
        e4 = e[128 + lane];  e5 = e[160 + lane];
        e6 = e[192 + lane];  e7 = e[224 + lane];
    }

    // ---- stage x = relu(emb[id]) and hidden h in shared ----
#pragma unroll
    for (int j = 0; j < 4; j++) {
        int i = t + j * 256;
        sh_x[i] = fmaxf(emb[(size_t)ids[0] * H + i], 0.0f);
        sh_hid[i] = h[i];
    }
    __syncthreads();

    // ---- S1: 6144 (row, matrix) tasks; 2-3 per warp, software-pipelined ----
    {
        int t0 = gw, t1 = gw + NWARPS, t2 = gw + 2 * NWARPS;
        TaskRegs A, B;
        const float4* vA; const float4* vB;
        int rowA = t0 >> 1, matA = t0 & 1;
        const float4* wpA = (const float4*)((matA ? Whh : Wih) + (size_t)rowA * H);
        vA = matA ? (const float4*)sh_hid : (const float4*)sh_x;
        task_load(A, wpA, lane);

        int rowB = t1 >> 1, matB = t1 & 1;
        const float4* wpB = (const float4*)((matB ? Whh : Wih) + (size_t)rowB * H);
        vB = matB ? (const float4*)sh_hid : (const float4*)sh_x;
        task_load(B, wpB, lane);

        float sA = task_dot(A, vA, lane);
        sA = warp_sum(sA);
        if (lane == 0) {
            if (matA) g_gh[rowA] = sA + __ldg(bhh + rowA);
            else      g_gi[rowA] = sA + __ldg(bih + rowA);
        }

        bool hasC = (t2 < NTASKS);
        int rowC = t2 >> 1, matC = t2 & 1;
        if (hasC) {
            const float4* wpC = (const float4*)((matC ? Whh : Wih) + (size_t)rowC * H);
            task_load(A, wpC, lane);           // reuse A regs
        }

        float sB = task_dot(B, vB, lane);
        sB = warp_sum(sB);
        if (lane == 0) {
            if (matB) g_gh[rowB] = sB + __ldg(bhh + rowB);
            else      g_gi[rowB] = sB + __ldg(bih + rowB);
        }

        if (hasC) {
            const float4* vC = matC ? (const float4*)sh_hid : (const float4*)sh_x;
            float sC = task_dot(A, vC, lane);
            sC = warp_sum(sC);
            if (lane == 0) {
                if (matC) g_gh[rowC] = sC + __ldg(bhh + rowC);
                else      g_gi[rowC] = sC + __ldg(bih + rowC);
            }
        }
    }
    grid_barrier(0);

    // ---- S2: h_new DISTRIBUTED (blocks 0..3 -> 1024 threads total) ----
    if (blockIdx.x < 4) {
        int i = blockIdx.x * 256 + t;
        float r = 1.0f / (1.0f + expf(-(g_gi[i] + g_gh[i])));
        float z = 1.0f / (1.0f + expf(-(g_gi[H + i] + g_gh[H + i])));
        float n = tanhf(g_gi[2 * H + i] + r * g_gh[2 * H + i]);
        float hn = (1.0f - z) * n + z * sh_hid[i];
        g_cat[i] = 0.0f;                       // unnormalized ctx accumulator
        g_cat[H + i] = hn;
        out[V + i] = hn;                       // output slot 2: h_new
    }
    if (blockIdx.x == 4 && t == 0) { g_sum[0] = 0.0f; g_Z[0] = 0.0f; }
    grid_barrier(1);

    // ---- S3: attn logits = dot(preloaded enc regs, h_new). Memory-free. ----
#pragma unroll
    for (int j = 0; j < 4; j++) sh_h[t + j * 256] = g_cat[H + t + j * 256];
    __syncthreads();
    if (gw < S) {
        const float4* hv = (const float4*)sh_h;
        float s = dot4(e0, hv[lane])       + dot4(e1, hv[32 + lane])
                + dot4(e2, hv[64 + lane])  + dot4(e3, hv[96 + lane])
                + dot4(e4, hv[128 + lane]) + dot4(e5, hv[160 + lane])
                + dot4(e6, hv[192 + lane]) + dot4(e7, hv[224 + lane]);
        s = warp_sum(s);
        if (lane == 0) g_attn[gw] = s;
    }
    grid_barrier(2);

    // ---- S4 (blocks<128): Wc preload first (for S5), then max (MUFU-free),
    //      own-chunk exp, unnormalized ctx accumulation + partial Z. ----
    TaskRegs C0, C1;                           // W_comb row halves for S5
    if (gw < H) {
        const float4* wv = (const float4*)(Wc + (size_t)gw * 2 * H);
        task_load(C0, wv, lane);
        task_load(C1, wv + 256, lane);
    }
    if (blockIdx.x < 128) {
        float m = -1e30f;
#pragma unroll
        for (int j = 0; j < 8; j++) m = fmaxf(m, g_attn[t + j * 256]);
        m = warp_max(m);
        if (lane == 0) sh_red[w] = m;
        __syncthreads();
        if (t < 32) {
            float x = (t < 8) ? sh_red[t] : -1e30f;
            x = warp_max(x);
            if (t == 0) sh_red[0] = x;
        }
        __syncthreads();
        float M = sh_red[0];

        int cb = blockIdx.x & 3;               // col block [0,4)
        int s0 = (blockIdx.x >> 2) * 64;       // s-chunk base
        if (t < 64) sh_a[t] = expf(g_attn[s0 + t] - M);
        __syncthreads();

        if (cb == 0) {                         // one col-block per chunk owns Z + g_e
            if (t < 64) g_e[s0 + t] = sh_a[t];
            if (t == 0) {
                float z = 0.f;
#pragma unroll
                for (int k = 0; k < 64; k++) z += sh_a[k];
                atomicAdd(&g_Z[0], z);
            }
        }
        int col = cb * 256 + t;
        float acc = 0.f;
#pragma unroll 8
        for (int s = 0; s < 64; s++)
            acc += sh_a[s] * enc[(size_t)(s0 + s) * H + col];   // L2-hot
        atomicAdd(&g_cat[col], acc);
    }
    grid_barrier(3);

    float invZ = 1.0f / g_Z[0];

    // ---- S5a: comb = tanh(Wc_row . [ctx*invZ ; h_new] + bc). Loads prefetched. ----
    if (gw < H) {
        const float4* vv = (const float4*)g_cat;
        float s0p = task_dot(C0, vv, lane);        // ctx half (unnormalized)
        float s1p = task_dot(C1, vv + 256, lane);  // h_new half
        float s = s0p * invZ + s1p;
        s = warp_sum(s);
        if (lane == 0) g_comb[gw] = tanhf(s + bc[gw]);
    }
    // ---- S5b: attn output (blocks 128..135 -> 2048 threads). ----
    if (blockIdx.x >= 128 && blockIdx.x < 136) {
        int i = (blockIdx.x - 128) * 256 + t;
        out[V + H + i] = g_e[i] * invZ;        // scalar store (misaligned base)
    }
}

// ===== Kernel B: vocab logits + fused exp-sum (full multi-wave grid) =====
__global__ void __launch_bounds__(256) k_vocab(
        const float* __restrict__ Wo, const float* __restrict__ bo,
        float* __restrict__ out) {
    __shared__ float sh_c[H];
    __shared__ float sh_e[8];
    int t = threadIdx.x;
#pragma unroll
    for (int j = 0; j < 4; j++) sh_c[t + j * 256] = g_comb[t + j * 256];
    __syncthreads();

    int w = t >> 5, lane = t & 31;
    int row = blockIdx.x * 8 + w;              // 6283 blocks
    float myexp = 0.f;
    if (row < V) {
        const float4* wv = (const float4*)(Wo + (size_t)row * H);
        const float4* c = (const float4*)sh_c;
        float4 a0 = __ldcs(wv + lane),       a1 = __ldcs(wv + 32 + lane),
               a2 = __ldcs(wv + 64 + lane),  a3 = __ldcs(wv + 96 + lane),
               a4 = __ldcs(wv + 128 + lane), a5 = __ldcs(wv + 160 + lane),
               a6 = __ldcs(wv + 192 + lane), a7 = __ldcs(wv + 224 + lane);
        float s = dot4(a0, c[lane])       + dot4(a1, c[32 + lane])
                + dot4(a2, c[64 + lane])  + dot4(a3, c[96 + lane])
                + dot4(a4, c[128 + lane]) + dot4(a5, c[160 + lane])
                + dot4(a6, c[192 + lane]) + dot4(a7, c[224 + lane]);
        s = warp_sum(s);
        if (lane == 0) {
            float logit = s + bo[row];
            out[row] = logit;
            myexp = expf(logit);               // logits tiny: no stabilization
        }
    }
    if (lane == 0) sh_e[w] = myexp;
    __syncthreads();
    if (t == 0) {
        float s = sh_e[0] + sh_e[1] + sh_e[2] + sh_e[3]
                + sh_e[4] + sh_e[5] + sh_e[6] + sh_e[7];
        atomicAdd(&g_sum[0], s);
    }
}

// ===== Kernel C: out[i] -= log(sum exp)  (V = 12564*4 + 1) =====
__global__ void __launch_bounds__(256) k_logprob(float* __restrict__ out) {
    int i = blockIdx.x * 256 + threadIdx.x;
    float lse = logf(g_sum[0]);
    float4* o4 = (float4*)out;
    if (i < 12564) {
        float4 v = o4[i];
        v.x -= lse; v.y -= lse; v.z -= lse; v.w -= lse;
        o4[i] = v;
    } else if (i == 12564) {
        out[V - 1] -= lse;
    }
}

extern "C" void kernel_launch(void* const* d_in, const int* in_sizes, int n_in,
                              void* d_out, int out_size) {
    const int*   ids  = (const int*)  d_in[0];
    const float* hid  = (const float*)d_in[1];
    const float* enc  = (const float*)d_in[2];
    const float* emb  = (const float*)d_in[3];
    const float* Wih  = (const float*)d_in[4];
    const float* Whh  = (const float*)d_in[5];
    const float* bih  = (const float*)d_in[6];
    const float* bhh  = (const float*)d_in[7];
    const float* Wc   = (const float*)d_in[8];
    const float* bc   = (const float*)d_in[9];
    const float* Wo   = (const float*)d_in[10];
    const float* bo   = (const float*)d_in[11];
    float* out = (float*)d_out;                // [log_probs V | h_new H | attn S]

    megaA<<<NBLOCKS, NTHREADS>>>(ids, emb, Wih, Whh, bih, bhh, hid,
                                 Wc, bc, enc, out);
    k_vocab<<<(V + 7) / 8, 256>>>(Wo, bo, out);
    k_logprob<<<(V / 4 + 256) / 256, 256>>>(out);
}